// round 2
// baseline (speedup 1.0000x reference)
#include <cuda_runtime.h>
#include <cuda_bf16.h>
#include <math.h>

// RoIPool: input [N=2, C=256, H=50, W=50] f32, rois [R=256, 5] f32
// output [R, C, 7, 7] f32. spatial_scale = 1/16.
// Semantics match torchvision MaxRoiPool / the JAX reference:
//   x1 = rint(roi_x1 * scale)  (round half to even, like jnp.round)
//   roi_w = max(x2 - x1 + 1, 1); bin edges floor/ceil, clamped to [0, W];
//   empty bin -> 0.

#define PH 7
#define PW 7
#define SCALE 0.0625f

__global__ void roipool_kernel(const float* __restrict__ input,
                               const float* __restrict__ rois,
                               float* __restrict__ out,
                               int C, int H, int W, int total) {
    int idx = blockIdx.x * blockDim.x + threadIdx.x;
    if (idx >= total) return;

    int pw = idx % PW;
    int t  = idx / PW;
    int ph = t % PH;
    t /= PH;
    int c = t % C;
    int r = t / C;

    const float* roi = rois + r * 5;
    int b  = (int)roi[0];
    int x1 = (int)rintf(roi[1] * SCALE);
    int y1 = (int)rintf(roi[2] * SCALE);
    int x2 = (int)rintf(roi[3] * SCALE);
    int y2 = (int)rintf(roi[4] * SCALE);

    float roi_w = (float)max(x2 - x1 + 1, 1);
    float roi_h = (float)max(y2 - y1 + 1, 1);
    float bw = roi_w * (1.0f / PW);
    float bh = roi_h * (1.0f / PH);

    int ws = min(max((int)floorf((float)pw * bw) + x1, 0), W);
    int we = min(max((int)ceilf((float)(pw + 1) * bw) + x1, 0), W);
    int hs = min(max((int)floorf((float)ph * bh) + y1, 0), H);
    int he = min(max((int)ceilf((float)(ph + 1) * bh) + y1, 0), H);

    const float* in = input + ((size_t)b * C + c) * (size_t)(H * W);

    float m = -INFINITY;
    for (int h = hs; h < he; ++h) {
        const float* row = in + h * W;
        for (int w = ws; w < we; ++w) {
            m = fmaxf(m, row[w]);
        }
    }
    // empty bin (or all -inf, impossible with finite input) -> 0
    if (he <= hs || we <= ws) m = 0.0f;
    out[idx] = m;
}

extern "C" void kernel_launch(void* const* d_in, const int* in_sizes, int n_in,
                              void* d_out, int out_size) {
    const float* input = (const float*)d_in[0];
    const float* rois  = (const float*)d_in[1];
    float* out = (float*)d_out;

    // Derive shapes: input elements = N*C*H*W with C=256,H=50,W=50; rois = R*5.
    const int C = 256, H = 50, W = 50;
    int R = in_sizes[1] / 5;
    int total = R * C * PH * PW;   // == out_size

    int threads = 256;
    int blocks = (total + threads - 1) / threads;
    roipool_kernel<<<blocks, threads>>>(input, rois, out, C, H, W, total);
}